// round 1
// baseline (speedup 1.0000x reference)
#include <cuda_runtime.h>
#include <math.h>

#define BB 64
#define SS 1024
#define EE 1024
#define DD 512

// Scratch (no allocation allowed in kernel_launch)
__device__ float g_hp[BB * DD];          // h_proj + bias, [B, D]
__device__ float g_pscore[4 * BB * SS];  // partial scores per d-tile

// ---------------------------------------------------------------------------
// K0: hp[b,d] = attn_b[d] + sum_k hidden[b,k] * attn_W[k, d]   (W_h = attn_W[:D])
// grid (D/128, B), block 128
// ---------------------------------------------------------------------------
__global__ void hproj_kernel(const float* __restrict__ hidden,
                             const float* __restrict__ attn_W,
                             const float* __restrict__ attn_b) {
    __shared__ float hrow[DD];
    int b = blockIdx.y;
    int d = blockIdx.x * 128 + threadIdx.x;
    for (int i = threadIdx.x; i < DD; i += 128) hrow[i] = hidden[b * DD + i];
    __syncthreads();
    float acc = attn_b[d];
#pragma unroll 8
    for (int k = 0; k < DD; k++) acc += hrow[k] * attn_W[k * DD + d];
    g_hp[b * DD + d] = acc;
}

// ---------------------------------------------------------------------------
// K1: fused e_proj GEMM + tanh + v-dot partial scores.
// Tile: BM=128 rows (b,s), BN=128 cols (d), K over E2=1024 in BK=16 steps.
// grid (4 d-tiles [x fastest -> L2 reuse of A tile], 512 row-tiles), 256 thr.
// Each thread: 8x8 register tile. Epilogue: ps[i] = sum_j v[n]*tanh(acc+hp[n]),
// reduced across the 16 tx-threads into g_pscore[dtile][row].
// ---------------------------------------------------------------------------
#define BM 128
#define BN 128
#define BK 16
#define PADW 132

__global__ __launch_bounds__(256) void scores_kernel(
    const float* __restrict__ enc,
    const float* __restrict__ attn_W,
    const float* __restrict__ vW) {
    const float* We = attn_W + DD * DD;  // W_e = attn_W[D:], shape [E2, D]
    __shared__ float As[BK][PADW];
    __shared__ float Bs[BK][PADW];
    __shared__ float red[BM][16];

    int dt = blockIdx.x;       // 0..3  (d tile)
    int rt = blockIdx.y;       // 0..511 (row tile)
    int r0 = rt * BM;
    int tid = threadIdx.x;
    int tx = tid & 15;         // n block
    int ty = tid >> 4;         // m block

    float acc[8][8];
#pragma unroll
    for (int i = 0; i < 8; i++)
#pragma unroll
        for (int j = 0; j < 8; j++) acc[i][j] = 0.f;

    const float* Aptr = enc + (size_t)r0 * EE;

    for (int kk = 0; kk < EE; kk += BK) {
        // Load A tile 128x16 (512 float4, 2 per thread), store transposed
#pragma unroll
        for (int l = 0; l < 2; l++) {
            int q = tid + l * 256;
            int row = q >> 2;
            int c4 = (q & 3) * 4;
            float4 v4 = *(const float4*)(Aptr + (size_t)row * EE + kk + c4);
            As[c4 + 0][row] = v4.x;
            As[c4 + 1][row] = v4.y;
            As[c4 + 2][row] = v4.z;
            As[c4 + 3][row] = v4.w;
        }
        // Load B tile 16x128 (512 float4, 2 per thread)
#pragma unroll
        for (int l = 0; l < 2; l++) {
            int q = tid + l * 256;
            int krow = q >> 5;          // 0..15
            int col = (q & 31) * 4;     // 0..124
            *(float4*)&Bs[krow][col] =
                *(const float4*)(We + (size_t)(kk + krow) * DD + dt * 128 + col);
        }
        __syncthreads();
#pragma unroll
        for (int k = 0; k < BK; k++) {
            float a[8], bv[8];
            *(float4*)&a[0]  = *(float4*)&As[k][ty * 8];
            *(float4*)&a[4]  = *(float4*)&As[k][ty * 8 + 4];
            *(float4*)&bv[0] = *(float4*)&Bs[k][tx * 8];
            *(float4*)&bv[4] = *(float4*)&Bs[k][tx * 8 + 4];
#pragma unroll
            for (int i = 0; i < 8; i++)
#pragma unroll
                for (int j = 0; j < 8; j++) acc[i][j] += a[i] * bv[j];
        }
        __syncthreads();
    }

    // Epilogue: energy = tanh(acc + hp), partial score = v . energy
    int b = r0 / SS;  // 128-row tile never crosses batch boundary (128 | 1024)
    float vv[8], hh[8];
#pragma unroll
    for (int j = 0; j < 8; j++) {
        int n = dt * 128 + tx * 8 + j;
        vv[j] = vW[n];
        hh[j] = g_hp[b * DD + n];
    }
#pragma unroll
    for (int i = 0; i < 8; i++) {
        float s = 0.f;
#pragma unroll
        for (int j = 0; j < 8; j++) s += vv[j] * tanhf(acc[i][j] + hh[j]);
        red[ty * 8 + i][tx] = s;
    }
    __syncthreads();
    if (tid < BM) {
        float s = 0.f;
#pragma unroll
        for (int t = 0; t < 16; t++) s += red[tid][t];
        g_pscore[dt * (BB * SS) + r0 + tid] = s;
    }
}

// ---------------------------------------------------------------------------
// K2: combine partial scores, mask, softmax over S per batch. grid(64), 256 thr
// ---------------------------------------------------------------------------
__global__ void softmax_kernel(const int* __restrict__ mask,
                               float* __restrict__ wout) {
    int b = blockIdx.x;
    __shared__ float sc[SS];
    __shared__ float redbuf[256];
    int tid = threadIdx.x;

    float lmax = -3.402823466e38f;
    for (int s = tid; s < SS; s += 256) {
        int idx = b * SS + s;
        float v = g_pscore[idx] + g_pscore[BB * SS + idx] +
                  g_pscore[2 * BB * SS + idx] + g_pscore[3 * BB * SS + idx];
        if (mask[idx] == 0) v = -3.402823466e38f;
        sc[s] = v;
        lmax = fmaxf(lmax, v);
    }
    redbuf[tid] = lmax;
    __syncthreads();
    for (int o = 128; o > 0; o >>= 1) {
        if (tid < o) redbuf[tid] = fmaxf(redbuf[tid], redbuf[tid + o]);
        __syncthreads();
    }
    float m = redbuf[0];
    __syncthreads();

    float lsum = 0.f;
    for (int s = tid; s < SS; s += 256) {
        float e = expf(sc[s] - m);
        sc[s] = e;
        lsum += e;
    }
    redbuf[tid] = lsum;
    __syncthreads();
    for (int o = 128; o > 0; o >>= 1) {
        if (tid < o) redbuf[tid] += redbuf[tid + o];
        __syncthreads();
    }
    float inv = 1.f / redbuf[0];
    for (int s = tid; s < SS; s += 256) wout[b * SS + s] = sc[s] * inv;
}

// ---------------------------------------------------------------------------
// K3: context[b,e] = sum_s w[b,s] * enc[b,s,e]. grid (E2/128, B), 128 thr.
// ---------------------------------------------------------------------------
__global__ void context_kernel(const float* __restrict__ enc,
                               const float* __restrict__ w,
                               float* __restrict__ ctx) {
    __shared__ float ws[SS];
    int b = blockIdx.y;
    int e = blockIdx.x * 128 + threadIdx.x;
    for (int i = threadIdx.x; i < SS; i += 128) ws[i] = w[b * SS + i];
    __syncthreads();
    float acc = 0.f;
    const float* p = enc + (size_t)b * SS * EE + e;
#pragma unroll 4
    for (int s = 0; s < SS; s++) acc += ws[s] * p[(size_t)s * EE];
    ctx[b * EE + e] = acc;
}

// ---------------------------------------------------------------------------
extern "C" void kernel_launch(void* const* d_in, const int* in_sizes, int n_in,
                              void* d_out, int out_size) {
    const float* hidden = (const float*)d_in[0];   // [B, D]
    const float* enc    = (const float*)d_in[1];   // [B, S, E2]
    const int*   mask   = (const int*)d_in[2];     // [B, S]
    const float* attn_W = (const float*)d_in[3];   // [E2+D, D]
    const float* attn_b = (const float*)d_in[4];   // [D]
    const float* v_W    = (const float*)d_in[5];   // [D]

    float* out = (float*)d_out;
    float* ctx = out;               // context [B, E2] first (tuple order)
    float* wts = out + BB * EE;     // attn_weights [B, S]

    hproj_kernel<<<dim3(DD / 128, BB), 128>>>(hidden, attn_W, attn_b);
    scores_kernel<<<dim3(4, (BB * SS) / BM), 256>>>(enc, attn_W, v_W);
    softmax_kernel<<<BB, 256>>>(mask, wts);
    context_kernel<<<dim3(EE / 128, BB), 128>>>(enc, wts, ctx);
}

// round 3
// speedup vs baseline: 3.0563x; 3.0563x over previous
#include <cuda_runtime.h>
#include <math.h>
#include <stdint.h>

#define BB 64
#define SS 1024
#define EE 1024
#define DD 512

// ---------------- device scratch ----------------
__device__ float g_hp[BB * DD];            // h_proj + bias  [B, D]
__device__ float g_WeT[DD * EE];           // W_e transposed [D(n), E2(k)]
__device__ float g_pscore[2 * BB * SS];    // per-n-tile score partials
__device__ float g_ctx_part[8 * BB * EE];  // context partials

// ---------------- async copy helpers ----------------
__device__ __forceinline__ uint32_t smem_u32(const void* p) {
    uint32_t a;
    asm("{ .reg .u64 t; cvta.to.shared.u64 t, %1; cvt.u32.u64 %0, t; }" : "=r"(a) : "l"(p));
    return a;
}
#define CP_ASYNC16(dst, src) \
    asm volatile("cp.async.cg.shared.global [%0], [%1], 16;" :: "r"(dst), "l"(src) : "memory")
#define CP_COMMIT() asm volatile("cp.async.commit_group;" ::: "memory")
#define CP_WAIT1()  asm volatile("cp.async.wait_group 1;" ::: "memory")
#define CP_WAIT0()  asm volatile("cp.async.wait_group 0;" ::: "memory")

__device__ __forceinline__ uint32_t f2tf32(float x) {
    uint32_t u;
    asm("cvt.rna.tf32.f32 %0, %1;" : "=r"(u) : "f"(x));
    return u;
}

__device__ __forceinline__ void mma_tf32(float c[4], uint32_t a0, uint32_t a1,
                                         uint32_t a2, uint32_t a3, uint32_t b0,
                                         uint32_t b1) {
    asm volatile(
        "mma.sync.aligned.m16n8k8.row.col.f32.tf32.tf32.f32 "
        "{%0,%1,%2,%3}, {%4,%5,%6,%7}, {%8,%9}, {%0,%1,%2,%3};"
        : "+f"(c[0]), "+f"(c[1]), "+f"(c[2]), "+f"(c[3])
        : "r"(a0), "r"(a1), "r"(a2), "r"(a3), "r"(b0), "r"(b1));
}

// ---------------- tiling ----------------
#define BM 128
#define BN 256
#define BK 32
#define NCHUNK (EE / BK)        // 32
#define ROWSTRIDE 36            // floats (32 data + 4 pad); 144B, 16B aligned
#define A_SZB (BM * ROWSTRIDE * 4)   // 18432
#define B_SZB (BN * ROWSTRIDE * 4)   // 36864
#define STAGE_B (A_SZB + B_SZB)      // 55296
#define OFF_SHP (2 * STAGE_B)                 // hp tile (256 floats)
#define OFF_SV  (OFF_SHP + BN * 4)            // v tile (256 floats)
#define OFF_RED (OFF_SV + BN * 4)             // red[128][17]
#define SMEM_SIZE (OFF_RED + 128 * 17 * 4)    // ~121 KB

// ---------------------------------------------------------------------------
// transpose W_e [E2, D] -> g_WeT [D, E2]
// ---------------------------------------------------------------------------
__global__ void transpose_we(const float* __restrict__ attn_W) {
    __shared__ float t[32][33];
    int k0 = blockIdx.x * 32, d0 = blockIdx.y * 32;
    for (int i = threadIdx.y; i < 32; i += 8)
        t[i][threadIdx.x] = attn_W[(size_t)(DD + k0 + i) * DD + d0 + threadIdx.x];
    __syncthreads();
    for (int i = threadIdx.y; i < 32; i += 8)
        g_WeT[(size_t)(d0 + i) * EE + k0 + threadIdx.x] = t[threadIdx.x][i];
}

// ---------------------------------------------------------------------------
// hp[b,d] = attn_b[d] + hidden[b,:] @ attn_W[:D, d]
// ---------------------------------------------------------------------------
__global__ void hproj_kernel(const float* __restrict__ hidden,
                             const float* __restrict__ attn_W,
                             const float* __restrict__ attn_b) {
    __shared__ float hrow[DD];
    int b = blockIdx.y;
    int d = blockIdx.x * 128 + threadIdx.x;
    for (int i = threadIdx.x; i < DD; i += 128) hrow[i] = hidden[b * DD + i];
    __syncthreads();
    float acc = attn_b[d];
#pragma unroll 8
    for (int k = 0; k < DD; k++) acc += hrow[k] * attn_W[k * DD + d];
    g_hp[b * DD + d] = acc;
}

// ---------------------------------------------------------------------------
// scores: tf32 mma.sync GEMM (BMxBN tile, K=1024) + fused tanh + v-dot.
// grid (2 n-tiles, 512 row-tiles), 256 threads (8 warps, each 64x64).
// ---------------------------------------------------------------------------
__global__ void __launch_bounds__(256, 1)
scores_mma_kernel(const float* __restrict__ enc, const float* __restrict__ vW) {
    extern __shared__ char smem[];
    uint32_t sb = smem_u32(smem);
    int tid = threadIdx.x;
    int wid = tid >> 5, lid = tid & 31;
    int gid = lid >> 2, tig = lid & 3;
    int wm = wid >> 2, wn = wid & 3;       // warp grid 2(m) x 4(n)
    int nt = blockIdx.x;                   // n tile (0..1)
    int r0 = blockIdx.y * BM;              // global row
    int b = r0 / SS;
    int n0 = nt * BN;

    float* shp = (float*)(smem + OFF_SHP);
    float* sv  = (float*)(smem + OFF_SV);
    for (int i = tid; i < BN; i += 256) {
        shp[i] = g_hp[b * DD + n0 + i];
        sv[i]  = vW[n0 + i];
    }

    const float* Abase = enc + (size_t)r0 * EE;
    const float* Bbase = g_WeT + (size_t)n0 * EE;

    // ---- async load of one K-chunk into stage st ----
    auto load_chunk = [&](int c, int st) {
        uint32_t sA = sb + st * STAGE_B;
        uint32_t sB = sA + A_SZB;
#pragma unroll
        for (int i = 0; i < 4; i++) {                 // A: 1024 16B chunks
            int idx = tid + i * 256;
            int row = idx >> 3, ch = idx & 7;
            CP_ASYNC16(sA + row * (ROWSTRIDE * 4) + ch * 16,
                       Abase + (size_t)row * EE + c * BK + ch * 4);
        }
#pragma unroll
        for (int i = 0; i < 8; i++) {                 // B: 2048 16B chunks
            int idx = tid + i * 256;
            int row = idx >> 3, ch = idx & 7;
            CP_ASYNC16(sB + row * (ROWSTRIDE * 4) + ch * 16,
                       Bbase + (size_t)row * EE + c * BK + ch * 4);
        }
        CP_COMMIT();
    };

    float acc[4][8][4];
#pragma unroll
    for (int mf = 0; mf < 4; mf++)
#pragma unroll
        for (int nf = 0; nf < 8; nf++)
#pragma unroll
            for (int q = 0; q < 4; q++) acc[mf][nf][q] = 0.f;

    load_chunk(0, 0);
    load_chunk(1, 1);

    for (int c = 0; c < NCHUNK; c++) {
        int st = c & 1;
        CP_WAIT1();
        __syncthreads();
        const float* fA = (const float*)(smem + st * STAGE_B);
        const float* fB = (const float*)(smem + st * STAGE_B + A_SZB);
#pragma unroll
        for (int k8 = 0; k8 < BK; k8 += 8) {
            uint32_t a[4][4], bb[8][2];
#pragma unroll
            for (int mf = 0; mf < 4; mf++) {
                int m0 = wm * 64 + mf * 16 + gid;
                a[mf][0] = f2tf32(fA[m0 * ROWSTRIDE + k8 + tig]);
                a[mf][1] = f2tf32(fA[(m0 + 8) * ROWSTRIDE + k8 + tig]);
                a[mf][2] = f2tf32(fA[m0 * ROWSTRIDE + k8 + tig + 4]);
                a[mf][3] = f2tf32(fA[(m0 + 8) * ROWSTRIDE + k8 + tig + 4]);
            }
#pragma unroll
            for (int nf = 0; nf < 8; nf++) {
                int nr = wn * 64 + nf * 8 + gid;
                bb[nf][0] = f2tf32(fB[nr * ROWSTRIDE + k8 + tig]);
                bb[nf][1] = f2tf32(fB[nr * ROWSTRIDE + k8 + tig + 4]);
            }
#pragma unroll
            for (int mf = 0; mf < 4; mf++)
#pragma unroll
                for (int nf = 0; nf < 8; nf++)
                    mma_tf32(acc[mf][nf], a[mf][0], a[mf][1], a[mf][2], a[mf][3],
                             bb[nf][0], bb[nf][1]);
        }
        __syncthreads();
        if (c + 2 < NCHUNK) load_chunk(c + 2, st);
    }
    CP_WAIT0();

    // ---- epilogue: score partial = sum_n v[n] * tanh(acc + hp[n]) ----
    float* red = (float*)(smem + OFF_RED);  // [128][17]
#pragma unroll
    for (int mf = 0; mf < 4; mf++) {
#pragma unroll
        for (int half = 0; half < 2; half++) {
            int r = wm * 64 + mf * 16 + half * 8 + gid;
            float s = 0.f;
#pragma unroll
            for (int nf = 0; nf < 8; nf++) {
                int nl = wn * 64 + nf * 8 + tig * 2;
                float e0 = acc[mf][nf][half * 2 + 0] + shp[nl];
                float e1 = acc[mf][nf][half * 2 + 1] + shp[nl + 1];
                float t0, t1;
                asm("tanh.approx.f32 %0, %1;" : "=f"(t0) : "f"(e0));
                asm("tanh.approx.f32 %0, %1;" : "=f"(t1) : "f"(e1));
                s = fmaf(sv[nl], t0, s);
                s = fmaf(sv[nl + 1], t1, s);
            }
            red[r * 17 + wn * 4 + tig] = s;
        }
    }
    __syncthreads();
    if (tid < BM) {
        float s = 0.f;
#pragma unroll
        for (int t = 0; t < 16; t++) s += red[tid * 17 + t];
        g_pscore[nt * (BB * SS) + r0 + tid] = s;
    }
}

// ---------------------------------------------------------------------------
// softmax: combine 2 partials, mask, softmax over S. grid(64), 256 threads.
// ---------------------------------------------------------------------------
__global__ void softmax_kernel(const int* __restrict__ mask,
                               float* __restrict__ wout) {
    int b = blockIdx.x;
    __shared__ float sc[SS];
    __shared__ float redbuf[256];
    int tid = threadIdx.x;

    float lmax = -3.402823466e38f;
    for (int s = tid; s < SS; s += 256) {
        int idx = b * SS + s;
        float v = g_pscore[idx] + g_pscore[BB * SS + idx];
        if (mask[idx] == 0) v = -3.402823466e38f;
        sc[s] = v;
        lmax = fmaxf(lmax, v);
    }
    redbuf[tid] = lmax;
    __syncthreads();
    for (int o = 128; o > 0; o >>= 1) {
        if (tid < o) redbuf[tid] = fmaxf(redbuf[tid], redbuf[tid + o]);
        __syncthreads();
    }
    float m = redbuf[0];
    __syncthreads();

    float lsum = 0.f;
    for (int s = tid; s < SS; s += 256) {
        float e = expf(sc[s] - m);
        sc[s] = e;
        lsum += e;
    }
    redbuf[tid] = lsum;
    __syncthreads();
    for (int o = 128; o > 0; o >>= 1) {
        if (tid < o) redbuf[tid] += redbuf[tid + o];
        __syncthreads();
    }
    float inv = 1.f / redbuf[0];
    for (int s = tid; s < SS; s += 256) wout[b * SS + s] = sc[s] * inv;
}

// ---------------------------------------------------------------------------
// context partials: grid (2, 8, 64), 128 threads; float4 per thread.
// ---------------------------------------------------------------------------
__global__ void __launch_bounds__(128) context_part_kernel(
    const float* __restrict__ enc, const float* __restrict__ w) {
    __shared__ float ws[128];
    int bx = blockIdx.x, sy = blockIdx.y, b = blockIdx.z;
    int e0 = bx * 512 + threadIdx.x * 4;
    ws[threadIdx.x] = w[b * SS + sy * 128 + threadIdx.x];
    __syncthreads();
    const float* base = enc + ((size_t)b * SS + sy * 128) * EE + e0;
    float4 acc = make_float4(0.f, 0.f, 0.f, 0.f);
#pragma unroll 4
    for (int r = 0; r < 128; r++) {
        float4 v = *(const float4*)(base + (size_t)r * EE);
        float c = ws[r];
        acc.x = fmaf(c, v.x, acc.x);
        acc.y = fmaf(c, v.y, acc.y);
        acc.z = fmaf(c, v.z, acc.z);
        acc.w = fmaf(c, v.w, acc.w);
    }
    *(float4*)&g_ctx_part[((size_t)sy * BB + b) * EE + e0] = acc;
}

__global__ void context_reduce_kernel(float* __restrict__ ctx) {
    int b = blockIdx.y;
    int e = blockIdx.x * 256 + threadIdx.x;
    float s = 0.f;
#pragma unroll
    for (int sy = 0; sy < 8; sy++) s += g_ctx_part[((size_t)sy * BB + b) * EE + e];
    ctx[b * EE + e] = s;
}

// ---------------------------------------------------------------------------
extern "C" void kernel_launch(void* const* d_in, const int* in_sizes, int n_in,
                              void* d_out, int out_size) {
    const float* hidden = (const float*)d_in[0];   // [B, D]
    const float* enc    = (const float*)d_in[1];   // [B, S, E2]
    const int*   mask   = (const int*)d_in[2];     // [B, S]
    const float* attn_W = (const float*)d_in[3];   // [E2+D, D]
    const float* attn_b = (const float*)d_in[4];   // [D]
    const float* v_W    = (const float*)d_in[5];   // [D]

    float* out = (float*)d_out;
    float* ctx = out;            // context [B, E2]
    float* wts = out + BB * EE;  // attn_weights [B, S]

    cudaFuncSetAttribute(scores_mma_kernel,
                         cudaFuncAttributeMaxDynamicSharedMemorySize, SMEM_SIZE);

    transpose_we<<<dim3(EE / 32, DD / 32), dim3(32, 8)>>>(attn_W);
    hproj_kernel<<<dim3(DD / 128, BB), 128>>>(hidden, attn_W, attn_b);
    scores_mma_kernel<<<dim3(2, (BB * SS) / BM), 256, SMEM_SIZE>>>(enc, v_W);
    softmax_kernel<<<BB, 256>>>(mask, wts);
    context_part_kernel<<<dim3(2, 8, BB), 128>>>(enc, wts);
    context_reduce_kernel<<<dim3(4, BB), 256>>>(ctx);
}

// round 4
// speedup vs baseline: 3.3120x; 1.0836x over previous
#include <cuda_runtime.h>
#include <math.h>
#include <stdint.h>

#define BB 64
#define SS 1024
#define EE 1024
#define DD 512

// ---------------- device scratch ----------------
__device__ float g_hp[BB * DD];            // h_proj + bias  [B, D]
__device__ float g_WeT[DD * EE];           // W_e^T, pre-rounded to tf32 [D(n), E2(k)]
__device__ float g_pscore[2 * BB * SS];    // per-n-tile score partials
__device__ float g_ctx_part[8 * BB * EE];  // context partials

// ---------------- helpers ----------------
__device__ __forceinline__ uint32_t smem_u32(const void* p) {
    uint32_t a;
    asm("{ .reg .u64 t; cvta.to.shared.u64 t, %1; cvt.u32.u64 %0, t; }" : "=r"(a) : "l"(p));
    return a;
}
#define CP_ASYNC16(dst, src) \
    asm volatile("cp.async.cg.shared.global [%0], [%1], 16;" :: "r"(dst), "l"(src) : "memory")
#define CP_COMMIT() asm volatile("cp.async.commit_group;" ::: "memory")
#define CP_WAIT2()  asm volatile("cp.async.wait_group 2;" ::: "memory")
#define CP_WAIT0()  asm volatile("cp.async.wait_group 0;" ::: "memory")

__device__ __forceinline__ uint32_t f2tf32(float x) {
    uint32_t u;
    asm("cvt.rna.tf32.f32 %0, %1;" : "=r"(u) : "f"(x));
    return u;
}

__device__ __forceinline__ void mma_tf32(float c[4], uint32_t a0, uint32_t a1,
                                         uint32_t a2, uint32_t a3, uint32_t b0,
                                         uint32_t b1) {
    asm volatile(
        "mma.sync.aligned.m16n8k8.row.col.f32.tf32.tf32.f32 "
        "{%0,%1,%2,%3}, {%4,%5,%6,%7}, {%8,%9}, {%0,%1,%2,%3};"
        : "+f"(c[0]), "+f"(c[1]), "+f"(c[2]), "+f"(c[3])
        : "r"(a0), "r"(a1), "r"(a2), "r"(a3), "r"(b0), "r"(b1));
}

// ---------------- tiling ----------------
#define BM 128
#define BN 256
#define BK 32
#define NCHUNK (EE / BK)        // 32
#define NSTAGE 3
#define ROWSTRIDE 36            // floats (32 data + 4 pad); conflict-free
#define A_SZB (BM * ROWSTRIDE * 4)   // 18432
#define B_SZB (BN * ROWSTRIDE * 4)   // 36864
#define STAGE_B (A_SZB + B_SZB)      // 55296
#define OFF_SHP (NSTAGE * STAGE_B)            // hp tile (256 floats)
#define OFF_SV  (OFF_SHP + BN * 4)            // v tile (256 floats)
#define OFF_RED (OFF_SV + BN * 4)             // red[128][17]
#define SMEM_SIZE (OFF_RED + 128 * 17 * 4)    // ~177 KB

// ---------------------------------------------------------------------------
// transpose W_e [E2, D] -> g_WeT [D, E2], pre-rounded to tf32 (rna)
// ---------------------------------------------------------------------------
__global__ void transpose_we(const float* __restrict__ attn_W) {
    __shared__ float t[32][33];
    int k0 = blockIdx.x * 32, d0 = blockIdx.y * 32;
    for (int i = threadIdx.y; i < 32; i += 8)
        t[i][threadIdx.x] = attn_W[(size_t)(DD + k0 + i) * DD + d0 + threadIdx.x];
    __syncthreads();
    for (int i = threadIdx.y; i < 32; i += 8)
        g_WeT[(size_t)(d0 + i) * EE + k0 + threadIdx.x] =
            __uint_as_float(f2tf32(t[threadIdx.x][i]));
}

// ---------------------------------------------------------------------------
// hp[b,d] = attn_b[d] + hidden[b,:] @ attn_W[:D, d]   (exact fp32)
// ---------------------------------------------------------------------------
__global__ void hproj_kernel(const float* __restrict__ hidden,
                             const float* __restrict__ attn_W,
                             const float* __restrict__ attn_b) {
    __shared__ float hrow[DD];
    int b = blockIdx.y;
    int d = blockIdx.x * 128 + threadIdx.x;
    for (int i = threadIdx.x; i < DD; i += 128) hrow[i] = hidden[b * DD + i];
    __syncthreads();
    float acc = attn_b[d];
#pragma unroll 8
    for (int k = 0; k < DD; k++) acc += hrow[k] * attn_W[k * DD + d];
    g_hp[b * DD + d] = acc;
}

// ---------------------------------------------------------------------------
// scores: tf32 mma.sync GEMM (128x256 tile, K=1024), 3-stage cp.async,
// no in-loop cvt (A truncated by HW, B pre-rounded). Fused tanh + v-dot.
// grid (2 n-tiles, 512 row-tiles), 256 threads (8 warps, each 64x64).
// ---------------------------------------------------------------------------
__global__ void __launch_bounds__(256, 1)
scores_mma_kernel(const float* __restrict__ enc, const float* __restrict__ vW) {
    extern __shared__ char smem[];
    uint32_t sb = smem_u32(smem);
    int tid = threadIdx.x;
    int wid = tid >> 5, lid = tid & 31;
    int gid = lid >> 2, tig = lid & 3;
    int wm = wid >> 2, wn = wid & 3;       // warp grid 2(m) x 4(n)
    int nt = blockIdx.x;                   // n tile (0..1)
    int r0 = blockIdx.y * BM;              // global row
    int b = r0 / SS;
    int n0 = nt * BN;

    float* shp = (float*)(smem + OFF_SHP);
    float* sv  = (float*)(smem + OFF_SV);
    for (int i = tid; i < BN; i += 256) {
        shp[i] = g_hp[b * DD + n0 + i];
        sv[i]  = vW[n0 + i];
    }

    const float* Abase = enc + (size_t)r0 * EE;
    const float* Bbase = g_WeT + (size_t)n0 * EE;

    auto load_chunk = [&](int c, int st) {
        uint32_t sA = sb + st * STAGE_B;
        uint32_t sB = sA + A_SZB;
#pragma unroll
        for (int i = 0; i < 4; i++) {                 // A: 1024 16B chunks
            int idx = tid + i * 256;
            int row = idx >> 3, ch = idx & 7;
            CP_ASYNC16(sA + row * (ROWSTRIDE * 4) + ch * 16,
                       Abase + (size_t)row * EE + c * BK + ch * 4);
        }
#pragma unroll
        for (int i = 0; i < 8; i++) {                 // B: 2048 16B chunks
            int idx = tid + i * 256;
            int row = idx >> 3, ch = idx & 7;
            CP_ASYNC16(sB + row * (ROWSTRIDE * 4) + ch * 16,
                       Bbase + (size_t)row * EE + c * BK + ch * 4);
        }
        CP_COMMIT();
    };

    float acc[4][8][4];
#pragma unroll
    for (int mf = 0; mf < 4; mf++)
#pragma unroll
        for (int nf = 0; nf < 8; nf++)
#pragma unroll
            for (int q = 0; q < 4; q++) acc[mf][nf][q] = 0.f;

    load_chunk(0, 0);
    load_chunk(1, 1);
    load_chunk(2, 2);

    int st = 0;
    for (int c = 0; c < NCHUNK; c++) {
        CP_WAIT2();
        __syncthreads();
        const float* fA = (const float*)(smem + st * STAGE_B);
        const float* fB = (const float*)(smem + st * STAGE_B + A_SZB);
#pragma unroll
        for (int k8 = 0; k8 < BK; k8 += 8) {
            uint32_t a[4][4], bb[8][2];
#pragma unroll
            for (int mf = 0; mf < 4; mf++) {
                int m0 = wm * 64 + mf * 16 + gid;
                a[mf][0] = __float_as_uint(fA[m0 * ROWSTRIDE + k8 + tig]);
                a[mf][1] = __float_as_uint(fA[(m0 + 8) * ROWSTRIDE + k8 + tig]);
                a[mf][2] = __float_as_uint(fA[m0 * ROWSTRIDE + k8 + tig + 4]);
                a[mf][3] = __float_as_uint(fA[(m0 + 8) * ROWSTRIDE + k8 + tig + 4]);
            }
#pragma unroll
            for (int nf = 0; nf < 8; nf++) {
                int nr = wn * 64 + nf * 8 + gid;
                bb[nf][0] = __float_as_uint(fB[nr * ROWSTRIDE + k8 + tig]);
                bb[nf][1] = __float_as_uint(fB[nr * ROWSTRIDE + k8 + tig + 4]);
            }
#pragma unroll
            for (int mf = 0; mf < 4; mf++)
#pragma unroll
                for (int nf = 0; nf < 8; nf++)
                    mma_tf32(acc[mf][nf], a[mf][0], a[mf][1], a[mf][2], a[mf][3],
                             bb[nf][0], bb[nf][1]);
        }
        __syncthreads();
        if (c + NSTAGE < NCHUNK) load_chunk(c + NSTAGE, st);
        st = (st == NSTAGE - 1) ? 0 : st + 1;
    }
    CP_WAIT0();

    // ---- epilogue: score partial = sum_n v[n] * tanh(acc + hp[n]) ----
    float* red = (float*)(smem + OFF_RED);  // [128][17]
#pragma unroll
    for (int mf = 0; mf < 4; mf++) {
#pragma unroll
        for (int half = 0; half < 2; half++) {
            int r = wm * 64 + mf * 16 + half * 8 + gid;
            float s = 0.f;
#pragma unroll
            for (int nf = 0; nf < 8; nf++) {
                int nl = wn * 64 + nf * 8 + tig * 2;
                float e0 = acc[mf][nf][half * 2 + 0] + shp[nl];
                float e1 = acc[mf][nf][half * 2 + 1] + shp[nl + 1];
                float t0, t1;
                asm("tanh.approx.f32 %0, %1;" : "=f"(t0) : "f"(e0));
                asm("tanh.approx.f32 %0, %1;" : "=f"(t1) : "f"(e1));
                s = fmaf(sv[nl], t0, s);
                s = fmaf(sv[nl + 1], t1, s);
            }
            red[r * 17 + wn * 4 + tig] = s;
        }
    }
    __syncthreads();
    if (tid < BM) {
        float s = 0.f;
#pragma unroll
        for (int t = 0; t < 16; t++) s += red[tid * 17 + t];
        g_pscore[nt * (BB * SS) + r0 + tid] = s;
    }
}

// ---------------------------------------------------------------------------
// softmax: combine 2 partials, mask, softmax over S. grid(64), 256 threads.
// ---------------------------------------------------------------------------
__global__ void softmax_kernel(const int* __restrict__ mask,
                               float* __restrict__ wout) {
    int b = blockIdx.x;
    __shared__ float sc[SS];
    __shared__ float redbuf[256];
    int tid = threadIdx.x;

    float lmax = -3.402823466e38f;
    for (int s = tid; s < SS; s += 256) {
        int idx = b * SS + s;
        float v = g_pscore[idx] + g_pscore[BB * SS + idx];
        if (mask[idx] == 0) v = -3.402823466e38f;
        sc[s] = v;
        lmax = fmaxf(lmax, v);
    }
    redbuf[tid] = lmax;
    __syncthreads();
    for (int o = 128; o > 0; o >>= 1) {
        if (tid < o) redbuf[tid] = fmaxf(redbuf[tid], redbuf[tid + o]);
        __syncthreads();
    }
    float m = redbuf[0];
    __syncthreads();

    float lsum = 0.f;
    for (int s = tid; s < SS; s += 256) {
        float e = expf(sc[s] - m);
        sc[s] = e;
        lsum += e;
    }
    redbuf[tid] = lsum;
    __syncthreads();
    for (int o = 128; o > 0; o >>= 1) {
        if (tid < o) redbuf[tid] += redbuf[tid + o];
        __syncthreads();
    }
    float inv = 1.f / redbuf[0];
    for (int s = tid; s < SS; s += 256) wout[b * SS + s] = sc[s] * inv;
}

// ---------------------------------------------------------------------------
// context partials: grid (2, 8, 64), 128 threads; float4 per thread.
// ---------------------------------------------------------------------------
__global__ void __launch_bounds__(128) context_part_kernel(
    const float* __restrict__ enc, const float* __restrict__ w) {
    __shared__ float ws[128];
    int bx = blockIdx.x, sy = blockIdx.y, b = blockIdx.z;
    int e0 = bx * 512 + threadIdx.x * 4;
    ws[threadIdx.x] = w[b * SS + sy * 128 + threadIdx.x];
    __syncthreads();
    const float* base = enc + ((size_t)b * SS + sy * 128) * EE + e0;
    float4 acc = make_float4(0.f, 0.f, 0.f, 0.f);
#pragma unroll 4
    for (int r = 0; r < 128; r++) {
        float4 v = *(const float4*)(base + (size_t)r * EE);
        float c = ws[r];
        acc.x = fmaf(c, v.x, acc.x);
        acc.y = fmaf(c, v.y, acc.y);
        acc.z = fmaf(c, v.z, acc.z);
        acc.w = fmaf(c, v.w, acc.w);
    }
    *(float4*)&g_ctx_part[((size_t)sy * BB + b) * EE + e0] = acc;
}

__global__ void context_reduce_kernel(float* __restrict__ ctx) {
    int b = blockIdx.y;
    int e = blockIdx.x * 256 + threadIdx.x;
    float s = 0.f;
#pragma unroll
    for (int sy = 0; sy < 8; sy++) s += g_ctx_part[((size_t)sy * BB + b) * EE + e];
    ctx[b * EE + e] = s;
}

// ---------------------------------------------------------------------------
extern "C" void kernel_launch(void* const* d_in, const int* in_sizes, int n_in,
                              void* d_out, int out_size) {
    const float* hidden = (const float*)d_in[0];   // [B, D]
    const float* enc    = (const float*)d_in[1];   // [B, S, E2]
    const int*   mask   = (const int*)d_in[2];     // [B, S]
    const float* attn_W = (const float*)d_in[3];   // [E2+D, D]
    const float* attn_b = (const float*)d_in[4];   // [D]
    const float* v_W    = (const float*)d_in[5];   // [D]

    float* out = (float*)d_out;
    float* ctx = out;            // context [B, E2]
    float* wts = out + BB * EE;  // attn_weights [B, S]

    cudaFuncSetAttribute(scores_mma_kernel,
                         cudaFuncAttributeMaxDynamicSharedMemorySize, SMEM_SIZE);

    transpose_we<<<dim3(EE / 32, DD / 32), dim3(32, 8)>>>(attn_W);
    hproj_kernel<<<dim3(DD / 128, BB), 128>>>(hidden, attn_W, attn_b);
    scores_mma_kernel<<<dim3(2, (BB * SS) / BM), 256, SMEM_SIZE>>>(enc, v_W);
    softmax_kernel<<<BB, 256>>>(mask, wts);
    context_part_kernel<<<dim3(2, 8, BB), 128>>>(enc, wts);
    context_reduce_kernel<<<dim3(4, BB), 256>>>(ctx);
}